// round 1
// baseline (speedup 1.0000x reference)
#include <cuda_runtime.h>
#include <stdint.h>

// Problem shape (fixed by the dataset): logits [B,C,H,W] f32, labels [B,H,W] i32
#define Bb 4
#define Cc 20
#define Hh 512
#define Ww 1024
#define HW (Hh * Ww)            // 524288
#define NPIX (Bb * HW)          // 2097152
#define NCLS 19                 // classes 1..19 (class 0 == ignore label)
#define NBINS 65536
#define BIN_SCALE 65536.0f
#define INV_BINS (1.0f / 65536.0f)

// Scratch (device globals, no dynamic allocation). 19*65536*8 = 10 MB, L2-resident.
__device__ unsigned long long g_hist[NCLS * NBINS];
__device__ float g_loss[NCLS];
__device__ float g_present[NCLS];

// ---------------------------------------------------------------------------
__global__ void zero_hist_kernel() {
    int i = blockIdx.x * blockDim.x + threadIdx.x;
    int stride = gridDim.x * blockDim.x;
    for (; i < NCLS * NBINS; i += stride) g_hist[i] = 0ull;
}

// ---------------------------------------------------------------------------
// One thread per pixel: softmax over 20 channels, then one packed u64 RED per
// class into the per-class error histogram. Ignored pixels (label==0) dropped.
__global__ void __launch_bounds__(256) hist_kernel(const float* __restrict__ logits,
                                                   const int* __restrict__ labels) {
    int p = blockIdx.x * blockDim.x + threadIdx.x;
    if (p >= NPIX) return;
    int lab = labels[p];
    if (lab == 0) return;  // ignore label: contributes exactly 0 to every class

    int b = p / HW;
    int hw = p - b * HW;
    const float* base = logits + (size_t)b * (Cc * HW) + hw;

    float v[Cc];
    float mx = -1e30f;
#pragma unroll
    for (int c = 0; c < Cc; c++) {
        v[c] = base[(size_t)c * HW];
        mx = fmaxf(mx, v[c]);
    }
    float s = 0.0f;
#pragma unroll
    for (int c = 0; c < Cc; c++) {
        v[c] = __expf(v[c] - mx);
        s += v[c];
    }
    float inv = 1.0f / s;

#pragma unroll
    for (int c = 1; c < Cc; c++) {
        float pc = v[c] * inv;
        bool fg = (c == lab);
        float e = fg ? (1.0f - pc) : pc;
        int bin = (int)(e * BIN_SCALE);
        bin = bin > (NBINS - 1) ? (NBINS - 1) : (bin < 0 ? 0 : bin);
        unsigned long long add = 1ull + (fg ? (1ull << 32) : 0ull);
        atomicAdd(&g_hist[(c - 1) * NBINS + bin], add);
    }
}

// ---------------------------------------------------------------------------
__device__ __forceinline__ unsigned long long warp_incl_scan_u64(unsigned long long x) {
#pragma unroll
    for (int d = 1; d < 32; d <<= 1) {
        unsigned long long y = __shfl_up_sync(0xffffffffu, x, d);
        if ((threadIdx.x & 31) >= d) x += y;
    }
    return x;
}

// One block per class. Descending scan over bins of packed (fg<<32 | count),
// accumulating e_bin * (J(after) - J(before)) for each nonzero bin.
// J(ct,cf) = 1 - (gts-cf)/(gts+ct-cf); J(0,0)=0 matches the reference's
// implicit jaccard[-1]=0, and jaccard is monotone so empty bins contribute 0.
__global__ void __launch_bounds__(1024) scan_kernel() {
    __shared__ unsigned long long warp_sums[32];
    __shared__ unsigned long long s_carry;
    __shared__ float red[32];

    const int cls = blockIdx.x;
    const unsigned long long* h = g_hist + (size_t)cls * NBINS;
    const int t = threadIdx.x;
    const int lane = t & 31;
    const int warp = t >> 5;

    // Phase 1: totals (gts in high 32, N_valid in low 32)
    unsigned long long tot = 0;
    for (int i = t; i < NBINS; i += 1024) tot += h[i];
#pragma unroll
    for (int d = 16; d; d >>= 1) tot += __shfl_down_sync(0xffffffffu, tot, d);
    if (lane == 0) warp_sums[warp] = tot;
    __syncthreads();
    if (warp == 0) {
        unsigned long long w = warp_sums[lane];
#pragma unroll
        for (int d = 16; d; d >>= 1) w += __shfl_down_sync(0xffffffffu, w, d);
        if (lane == 0) warp_sums[0] = w;
    }
    __syncthreads();
    unsigned long long total = warp_sums[0];
    unsigned int gts = (unsigned int)(total >> 32);

    if (gts == 0) {
        if (t == 0) { g_loss[cls] = 0.0f; g_present[cls] = 0.0f; }
        return;
    }
    const float fgts = (float)gts;

    __syncthreads();  // warp_sums[0] consumed; safe to reuse below
    if (t == 0) s_carry = 0ull;
    __syncthreads();

    float contrib = 0.0f;
#pragma unroll 1
    for (int j = 0; j < NBINS / 1024; j++) {
        int bin = (NBINS - 1) - (j * 1024 + t);  // descending error order
        unsigned long long v = h[bin];
        unsigned long long sc = warp_incl_scan_u64(v);
        if (lane == 31) warp_sums[warp] = sc;
        __syncthreads();
        if (warp == 0) {
            unsigned long long w = warp_incl_scan_u64(warp_sums[lane]);
            warp_sums[lane] = w;
        }
        __syncthreads();
        unsigned long long offset = (warp > 0 ? warp_sums[warp - 1] : 0ull) + s_carry;
        unsigned long long incl = sc + offset;

        unsigned int n = (unsigned int)(v & 0xffffffffull);
        if (n) {
            unsigned int f = (unsigned int)(v >> 32);
            unsigned int ct_a = (unsigned int)(incl & 0xffffffffull);
            unsigned int cf_a = (unsigned int)(incl >> 32);
            unsigned int ct_b = ct_a - n;
            unsigned int cf_b = cf_a - f;
            // counts < 2^24 -> exact in float
            float Ja = 1.0f - (fgts - (float)cf_a) / (fgts + (float)ct_a - (float)cf_a);
            float Jb = 1.0f - (fgts - (float)cf_b) / (fgts + (float)ct_b - (float)cf_b);
            float e = ((float)bin + 0.5f) * INV_BINS;  // bin-center representative
            contrib += e * (Ja - Jb);
        }
        __syncthreads();
        if (t == 0) s_carry += warp_sums[31];  // chunk total
        __syncthreads();
    }

    // Block-reduce contributions
#pragma unroll
    for (int d = 16; d; d >>= 1) contrib += __shfl_down_sync(0xffffffffu, contrib, d);
    if (lane == 0) red[warp] = contrib;
    __syncthreads();
    if (warp == 0) {
        float x = red[lane];
#pragma unroll
        for (int d = 16; d; d >>= 1) x += __shfl_down_sync(0xffffffffu, x, d);
        if (lane == 0) { g_loss[cls] = x; g_present[cls] = 1.0f; }
    }
}

// ---------------------------------------------------------------------------
__global__ void final_kernel(float* __restrict__ out) {
    float num = 0.0f, den = 0.0f;
#pragma unroll
    for (int c = 0; c < NCLS; c++) {
        num += g_loss[c] * g_present[c];
        den += g_present[c];
    }
    out[0] = num / fmaxf(den, 1.0f);
}

// ---------------------------------------------------------------------------
extern "C" void kernel_launch(void* const* d_in, const int* in_sizes, int n_in,
                              void* d_out, int out_size) {
    const float* logits = (const float*)d_in[0];
    const int* labels = (const int*)d_in[1];
    float* out = (float*)d_out;

    zero_hist_kernel<<<1024, 256>>>();
    hist_kernel<<<(NPIX + 255) / 256, 256>>>(logits, labels);
    scan_kernel<<<NCLS, 1024>>>();
    final_kernel<<<1, 1>>>(out);
}